// round 12
// baseline (speedup 1.0000x reference)
#include <cuda_runtime.h>
#include <cuda_bf16.h>
#include <math.h>
#include <stdint.h>

#define NN 100000
#define NE 1000000
#define D  64
#define H  128
#define NL 4
#define NG 64
#define TILE_E 128
#define NT ((NE + TILE_E - 1) / TILE_E)   // 7813
#define EGRID 148
#define ETHREADS 512
#define M1P 132          // float pitch, j-major (row = 528 B, 16B aligned)

typedef unsigned long long ull;

// ---------------- persistent device scratch ----------------
__device__ float g_h[NN * D];
__device__ float g_PQ[NN * 256];     // P (cols 0..127) | Q (cols 128..255)
__device__ float g_agg[NN * D];
__device__ float g_rbf[(size_t)NE * 16];
__device__ int   g_kind[NE];
__device__ float g_kt[NL * 2 * H];
__device__ float g_sums[NG * D];
__device__ float g_cnt[NG];

// ---------------- helpers ----------------
#define PACK2(d, x, y) asm("mov.b64 %0, {%1,%2};" : "=l"(d) : "r"(__float_as_uint(x)), "r"(__float_as_uint(y)))
#define UNPK2(lo, hi, v) asm("mov.b64 {%0,%1}, %2;" : "=r"(lo), "=r"(hi) : "l"(v))
#define FMA2(acc, a, b) asm("fma.rn.f32x2 %0, %1, %2, %0;" : "+l"(acc) : "l"(a), "l"(b))
#define ADD2(d, a, b)   asm("add.rn.f32x2 %0, %1, %2;" : "=l"(d) : "l"(a), "l"(b))
#define REDV2(p, v0, v1) \
    asm volatile("red.global.add.v2.f32 [%0], {%1,%2};" \
        :: "l"(p), "f"(v0), "f"(v1) : "memory")
#define BAR_ARRIVE(id, cnt) asm volatile("bar.arrive %0, %1;" :: "r"(id), "r"(cnt) : "memory")
#define BAR_SYNC(id, cnt)   asm volatile("bar.sync %0, %1;"   :: "r"(id), "r"(cnt) : "memory")
#define MEMBAR_CTA()        asm volatile("membar.cta;" ::: "memory")

// ---------------- init: node embed + zero everything ----------------
__global__ void k_init_h(const int* __restrict__ atoms, const float* __restrict__ embed) {
    int i = blockIdx.x * blockDim.x + threadIdx.x;
    if (i < NN * D) {
        g_h[i] = embed[atoms[i >> 6] * D + (i & 63)];
        g_agg[i] = 0.f;
    }
    if (i < NG * D) g_sums[i] = 0.f;
    if (i < NG) g_cnt[i] = 0.f;
}

// ---------------- edge prep (rbf + kind) + kind-table ----------------
__global__ void k_edge_prep(const int* __restrict__ ei, const float* __restrict__ coord,
                            const int* __restrict__ isr,
                            const float* __restrict__ subw, const float* __restrict__ W1,
                            const float* __restrict__ b1) {
    int e = blockIdx.x * blockDim.x + threadIdx.x;
    if (e < NE) {
        int s = ei[e], d = ei[NE + e];
        float dx = coord[s * 3 + 0] - coord[d * 3 + 0];
        float dy = coord[s * 3 + 1] - coord[d * 3 + 1];
        float dz = coord[s * 3 + 2] - coord[d * 3 + 2];
        float dist = sqrtf(dx * dx + dy * dy + dz * dz);
        const float coeff = -4.5f;
        float o[16];
#pragma unroll
        for (int g = 0; g < 16; g++) {
            float t = dist - (float)g * (5.0f / 15.0f);
            o[g] = __expf(coeff * t * t);
        }
        float4* dp = (float4*)&g_rbf[(size_t)e * 16];
        dp[0] = make_float4(o[0], o[1], o[2], o[3]);
        dp[1] = make_float4(o[4], o[5], o[6], o[7]);
        dp[2] = make_float4(o[8], o[9], o[10], o[11]);
        dp[3] = make_float4(o[12], o[13], o[14], o[15]);
        g_kind[e] = (isr[s] != isr[d]) ? 1 : 0;
    } else {
        int t = e - NE;
        if (t < NL * 2 * H) {
            int l = t >> 8, kind = (t >> 7) & 1, j = t & 127;
            const float* W1l = W1 + (size_t)l * 160 * H;
            float v = b1[l * H + j];
#pragma unroll
            for (int g = 0; g < 16; g++)
                v += subw[kind * 16 + g] * W1l[(144 + g) * H + j];
            g_kt[t] = v;
        }
    }
}

// ---------------- node GEMM + fused relu(h+agg) ----------------
__global__ __launch_bounds__(256) void k_nodegemm(const float* __restrict__ W1, int l) {
    __shared__ float sW[64 * H];
    __shared__ float sh[64 * 18];
    const float* W1l = W1 + (size_t)l * 160 * H;
    int tid = threadIdx.x;
    int n0 = blockIdx.x * 16;
    for (int i = tid; i < 16 * 64; i += 256) {
        int k = i & 63, e = i >> 6;
        size_t idx = (size_t)(n0 + e) * D + k;
        float hv = g_h[idx];
        if (l > 0) {
            hv = fmaxf(hv + g_agg[idx], 0.f);
            g_h[idx] = hv;
            g_agg[idx] = 0.f;
        }
        sh[k * 18 + e] = hv;
    }
    int j = tid & 127;
    int ng = tid >> 7;
    for (int pass = 0; pass < 2; pass++) {
        __syncthreads();
        for (int i = tid; i < 64 * H; i += 256) sW[i] = W1l[pass * 64 * H + i];
        __syncthreads();
        ull acc[4];
#pragma unroll
        for (int q = 0; q < 4; q++) acc[q] = 0ull;
#pragma unroll 8
        for (int k = 0; k < 64; k++) {
            float w = sW[k * H + j];
            ull ww; PACK2(ww, w, w);
#pragma unroll
            for (int q = 0; q < 4; q++) {
                ull hv = *(const ull*)&sh[k * 18 + ng * 8 + q * 2];
                FMA2(acc[q], hv, ww);
            }
        }
#pragma unroll
        for (int q = 0; q < 4; q++) {
            uint32_t lo, hi; UNPK2(lo, hi, acc[q]);
            int nb = n0 + ng * 8 + q * 2;
            g_PQ[(size_t)nb * 256 + pass * 128 + j] = __uint_as_float(lo);
            g_PQ[(size_t)(nb + 1) * 256 + pass * 128 + j] = __uint_as_float(hi);
        }
    }
}

// ---------------- warp-specialized persistent edge kernel ----------------
// smem byte offsets
#define OFF_M1    0          // 2 x float[128][132] = 2 x 67584
#define M1_BUF    67584
#define OFF_W2    135168     // 32768
#define OFF_RBF   167936     // 2 x ull[128*16] = 2 x 16384 (duplicated pairs)
#define RBF_BUF   16384
#define OFF_DST   200704     // 2 x 512
#define OFF_SRC   201728     // 2 x 512
#define OFF_KND   202752     // 2 x 512
#define SMEM_EDGE 203776

// named barriers: 1 = producer-internal, FULL = 2+buf, EMPTY = 4+buf
__global__ __launch_bounds__(ETHREADS, 1) void k_edge(const float* __restrict__ W1,
                                                      const float* __restrict__ W2,
                                                      const float* __restrict__ b2,
                                                      const int* __restrict__ ei, int l) {
    extern __shared__ char smem[];
    float* sW2 = (float*)(smem + OFF_W2);

    int tid = threadIdx.x;
    const float* W1l = W1 + (size_t)l * 160 * H;
    const float* W2l = W2 + (size_t)l * H * D;

    for (int i = tid; i < H * D; i += ETHREADS) sW2[i] = W2l[i];
    __syncthreads();

    const int chunk = (NT + EGRID - 1) / EGRID;   // 53
    int t0 = blockIdx.x * chunk;
    int t1 = t0 + chunk; if (t1 > NT) t1 = NT;
    if (t0 >= t1) return;
    const int ntile = t1 - t0;

    if (tid < 256) {
        // ================= PRODUCER (warps 0-7) =================
        const int a = tid;
        const int jp = a & 63;          // cols (jp, jp+64)
        const int grp = a >> 6;         // 4 groups of 32 edges
        const int eb = grp * 32;

        // hoisted per-layer constants
        ull w1c2[16];
#pragma unroll
        for (int g = 0; g < 16; g++) {
            const float* W1c = W1l + (128 + g) * H;
            PACK2(w1c2[g], W1c[jp], W1c[jp + 64]);
        }
        ull ktv0, ktv1;
        {
            const float* ktp = g_kt + l * 256;
            PACK2(ktv0, ktp[jp], ktp[jp + 64]);
            PACK2(ktv1, ktp[128 + jp], ktp[192 + jp]);
        }

        for (int tt = 0; tt < ntile; tt++) {
            int t = t0 + tt;
            int buf = tt & 1;
            if (tt >= 2) BAR_SYNC(4 + buf, 512);   // wait consumer freed buffer

            int* sDst = (int*)(smem + OFF_DST + buf * 512);
            int* sSrc = (int*)(smem + OFF_SRC + buf * 512);
            int* sKnd = (int*)(smem + OFF_KND + buf * 512);
            ull* sRbf = (ull*)(smem + OFF_RBF + buf * RBF_BUF);
            float* sM1 = (float*)(smem + OFF_M1 + buf * M1_BUF);

            // ---- stage meta + duplicated rbf (256 producer threads) ----
            int e0 = t * TILE_E;
            if (a < TILE_E) {
                int e = e0 + a;
                bool v = e < NE;
                sSrc[a] = v ? ei[e] : 0;
                sDst[a] = v ? ei[NE + e] : -1;
                sKnd[a] = v ? g_kind[e] : 0;
            }
#pragma unroll
            for (int q = 0; q < 2; q++) {
                int i = a * 2 + q;   // 512 float4 total
                int e = e0 + (i >> 2);
                float4 r = (e < NE) ? ((const float4*)g_rbf)[(size_t)t * 512 + i]
                                    : make_float4(0.f, 0.f, 0.f, 0.f);
                ull* rp = &sRbf[(size_t)i * 4];
                PACK2(rp[0], r.x, r.x);
                PACK2(rp[1], r.y, r.y);
                PACK2(rp[2], r.z, r.z);
                PACK2(rp[3], r.w, r.w);
            }
            BAR_SYNC(1, 256);   // producer-internal

            // ---- compute m1 ----
#pragma unroll 4
            for (int ee = 0; ee < 32; ee++) {
                int e = eb + ee;
                int dn = sDst[e], sn = sSrc[e];
                const float* Pp = g_PQ + (size_t)(dn < 0 ? 0 : dn) * 256;
                const float* Qp = g_PQ + (size_t)sn * 256 + 128;
                float p0 = Pp[jp], p1 = Pp[jp + 64];
                float q0 = Qp[jp], q1 = Qp[jp + 64];
                ull acc;
                PACK2(acc, p0 + q0, p1 + q1);
                ADD2(acc, acc, sKnd[e] ? ktv1 : ktv0);
                const ulonglong2* rb = (const ulonglong2*)&sRbf[(size_t)e * 16];
#pragma unroll
                for (int g = 0; g < 8; g++) {
                    ulonglong2 rv = rb[g];
                    FMA2(acc, rv.x, w1c2[2 * g]);
                    FMA2(acc, rv.y, w1c2[2 * g + 1]);
                }
                uint32_t u0, u1; UNPK2(u0, u1, acc);
                float x0 = __uint_as_float(u0), x1 = __uint_as_float(u1);
                sM1[jp * M1P + e]        = __fdividef(x0, 1.f + __expf(-x0));
                sM1[(jp + 64) * M1P + e] = __fdividef(x1, 1.f + __expf(-x1));
            }
            MEMBAR_CTA();
            BAR_ARRIVE(2 + buf, 512);   // buffer full
        }
    } else {
        // ================= CONSUMER (warps 8-15) =================
        const int c = tid - 256;
        const int dd = (c & 31) * 2;         // d-pair
        const int ebase = (c >> 5) * 16;     // 16 edges
        ull bp0, bp1;
        {
            float b0 = b2[l * D + dd], b1v = b2[l * D + dd + 1];
            PACK2(bp0, b0, b0);
            PACK2(bp1, b1v, b1v);
        }

        for (int tt = 0; tt < ntile; tt++) {
            int buf = tt & 1;
            BAR_SYNC(2 + buf, 512);   // wait buffer full

            const char* mbase = smem + OFF_M1 + buf * M1_BUF + ebase * 4;
            const int* sDst = (const int*)(smem + OFF_DST + buf * 512);

            ull acc[16];
#pragma unroll
            for (int q = 0; q < 16; q++) acc[q] = 0ull;
#pragma unroll 2
            for (int j = 0; j < H; j++) {
                const ulonglong2* mp = (const ulonglong2*)(mbase + j * (M1P * 4));
                ulonglong2 mA = mp[0], mB = mp[1], mC = mp[2], mD = mp[3];
                float2 wf = *(const float2*)&sW2[j * 64 + dd];
                ull w0, w1;
                PACK2(w0, wf.x, wf.x);
                PACK2(w1, wf.y, wf.y);
                FMA2(acc[0],  mA.x, w0); FMA2(acc[1],  mA.x, w1);
                FMA2(acc[2],  mA.y, w0); FMA2(acc[3],  mA.y, w1);
                FMA2(acc[4],  mB.x, w0); FMA2(acc[5],  mB.x, w1);
                FMA2(acc[6],  mB.y, w0); FMA2(acc[7],  mB.y, w1);
                FMA2(acc[8],  mC.x, w0); FMA2(acc[9],  mC.x, w1);
                FMA2(acc[10], mC.y, w0); FMA2(acc[11], mC.y, w1);
                FMA2(acc[12], mD.x, w0); FMA2(acc[13], mD.x, w1);
                FMA2(acc[14], mD.y, w0); FMA2(acc[15], mD.y, w1);
            }
            uint32_t a0, a1, b0u, b1u;
#pragma unroll
            for (int p = 0; p < 8; p++) {
                ADD2(acc[2 * p], acc[2 * p], bp0);
                ADD2(acc[2 * p + 1], acc[2 * p + 1], bp1);
                int eA = ebase + 2 * p;
                int dnA = sDst[eA], dnB = sDst[eA + 1];
                UNPK2(a0, b0u, acc[2 * p]);       // d0: (edge even, edge odd)
                UNPK2(a1, b1u, acc[2 * p + 1]);   // d1
                if (dnA >= 0)
                    REDV2(&g_agg[(size_t)dnA * D + dd], __uint_as_float(a0), __uint_as_float(a1));
                if (dnB >= 0)
                    REDV2(&g_agg[(size_t)dnB * D + dd], __uint_as_float(b0u), __uint_as_float(b1u));
            }
            if (tt < ntile - 2) BAR_ARRIVE(4 + buf, 512);   // buffer empty
        }
    }
}

// ---------------- pooling (relu fused) ----------------
__global__ void k_pool(const int* __restrict__ batch) {
    int i = blockIdx.x * blockDim.x + threadIdx.x;
    if (i >= NN * D) return;
    int n = i >> 6, d = i & 63;
    float v = fmaxf(g_h[i] + g_agg[i], 0.f);
    atomicAdd(&g_sums[batch[n] * D + d], v);
}

__global__ void k_count(const int* __restrict__ batch) {
    int n = blockIdx.x * blockDim.x + threadIdx.x;
    if (n >= NN) return;
    int b = batch[n];
    unsigned mask = __activemask();
    unsigned m = __match_any_sync(mask, b);
    int leader = __ffs(m) - 1;
    if ((threadIdx.x & 31) == leader) atomicAdd(&g_cnt[b], (float)__popc(m));
}

__global__ void k_final(const float* __restrict__ fcw, const float* __restrict__ fcb,
                        float* __restrict__ out) {
    int g = threadIdx.x;
    if (g < NG) {
        float c = fmaxf(g_cnt[g], 1.f);
        float s = 0.f;
#pragma unroll
        for (int d = 0; d < D; d++) s += g_sums[g * D + d] * fcw[d];
        out[g] = s / c + fcb[0];
    }
}

extern "C" void kernel_launch(void* const* d_in, const int* in_sizes, int n_in,
                              void* d_out, int out_size) {
    const int*   atoms = (const int*)d_in[0];
    const int*   ei    = (const int*)d_in[1];
    const float* coord = (const float*)d_in[2];
    const int*   isr   = (const int*)d_in[3];
    const int*   batch = (const int*)d_in[4];
    const float* embed = (const float*)d_in[5];
    const float* subw  = (const float*)d_in[6];
    const float* W1    = (const float*)d_in[7];
    const float* b1    = (const float*)d_in[8];
    const float* W2    = (const float*)d_in[9];
    const float* b2    = (const float*)d_in[10];
    const float* fcw   = (const float*)d_in[11];
    const float* fcb   = (const float*)d_in[12];
    float* out = (float*)d_out;

    cudaFuncSetAttribute(k_edge, cudaFuncAttributeMaxDynamicSharedMemorySize, SMEM_EDGE);

    const int T = 256;
    k_init_h<<<(NN * D + T - 1) / T, T>>>(atoms, embed);                       // 0
    k_edge_prep<<<(NE + 1024 + T - 1) / T, T>>>(ei, coord, isr, subw, W1, b1); // 1

    for (int l = 0; l < NL; l++) {
        k_nodegemm<<<NN / 16, 256>>>(W1, l);                                   // 2,4,6,8
        k_edge<<<EGRID, ETHREADS, SMEM_EDGE>>>(W1, W2, b2, ei, l);             // 3,5,7,9
    }

    k_pool<<<(NN * D + T - 1) / T, T>>>(batch);
    k_count<<<(NN + T - 1) / T, T>>>(batch);
    k_final<<<1, 64>>>(fcw, fcb, out);
}